// round 11
// baseline (speedup 1.0000x reference)
#include <cuda_runtime.h>
#include <cstdint>

// Problem constants (fixed by setup_inputs)
#define BATCH 4
#define LEN   2048
#define DIM   64
#define KMAX  64
#define QB    16       // queries per block in the find kernel

// Packed key bits per token: uint2 = (lo bits d0..31, hi bits d32..63).
__device__ uint2 g_keys[BATCH * LEN];

// ---------------------------------------------------------------------------
// Kernel 1: pack key sign bits. One warp per token, two ballots.
// ---------------------------------------------------------------------------
__global__ void pack_keys_kernel(const float* __restrict__ key_up) {
    int warp = (blockIdx.x * blockDim.x + threadIdx.x) >> 5;
    int lane = threadIdx.x & 31;
    if (warp >= BATCH * LEN) return;
    const float* p = key_up + (size_t)warp * DIM;
    unsigned lo = __ballot_sync(0xFFFFFFFFu, p[lane]      > 0.0f);
    unsigned hi = __ballot_sync(0xFFFFFFFFu, p[lane + 32] > 0.0f);
    if (lane == 0) g_keys[warp] = make_uint2(lo, hi);
}

// ---------------------------------------------------------------------------
// Kernel 2: candidate scan -- keys in registers, queries in registers.
// Block = 256 threads = 16 queries; grid = 512 blocks (4096 warps, ~28/SM).
// Each thread owns 8 packed keys (4x LDG.128, L2-broadcast). The block's 16
// queries are ballot-packed into 128B of smem, then hoisted to registers in
// every thread. Hot loop = 16x8 register compares, NO memory / cross-lane
// ops. Suspicion mask reduced via (statistically never-taken) smem atomicOr.
// Fast path: one coalesced STG.128/thread of -1.0f covers the 4KB output.
// Rare path: warp 0 runs the exact ordered ballot scan (R7 semantics) per
// suspect query from g_keys; non-suspects blanket-written. Output = float32.
// ---------------------------------------------------------------------------
__global__ void __launch_bounds__(256, 4)
find_cands_kernel(const float* __restrict__ query_up, float* __restrict__ out) {
    __shared__ uint2    s_q[QB];
    __shared__ unsigned s_susp;

    int t    = threadIdx.x;
    int warp = t >> 5;
    int lane = t & 31;
    int b    = blockIdx.x >> 7;                 // 128 blocks per batch
    int qgrp = blockIdx.x & 127;
    int q0   = b * LEN + qgrp * QB;             // first query (global token id)

    if (t == 0) s_susp = 0u;

    // --- Load this thread's 8 keys: 4 coalesced LDG.128 (L2-resident) ---
    const uint4* gk4 = (const uint4*)(g_keys + (size_t)b * LEN);  // 1024 uint4
    uint4 k0 = gk4[t];
    uint4 k1 = gk4[t + 256];
    uint4 k2 = gk4[t + 512];
    uint4 k3 = gk4[t + 768];

    // --- Pack the block's 16 queries: warp w packs queries 2w, 2w+1 ---
    {
        const float* qp = query_up + (size_t)(q0 + 2 * warp) * DIM;
        unsigned lo0 = __ballot_sync(0xFFFFFFFFu, qp[lane]       > 0.0f);
        unsigned hi0 = __ballot_sync(0xFFFFFFFFu, qp[lane + 32]  > 0.0f);
        unsigned lo1 = __ballot_sync(0xFFFFFFFFu, qp[lane + 64]  > 0.0f);
        unsigned hi1 = __ballot_sync(0xFFFFFFFFu, qp[lane + 96]  > 0.0f);
        if (lane == 0) {
            s_q[2 * warp]     = make_uint2(lo0, hi0);
            s_q[2 * warp + 1] = make_uint2(lo1, hi1);
        }
    }
    __syncthreads();

    // Hoist all 16 query bit-pairs into registers (uniform across block)
    unsigned qlo[QB], qhi[QB];
    #pragma unroll
    for (int i = 0; i < QB; ++i) { qlo[i] = s_q[i].x; qhi[i] = s_q[i].y; }

    // --- Hot loop: pure register compares, susp bit i = "query i matched" ---
    unsigned susp = 0u;
    #pragma unroll
    for (int i = 0; i < QB; ++i) {
        bool m = (k0.x == qlo[i]) | (k0.y == qhi[i]) |
                 (k0.z == qlo[i]) | (k0.w == qhi[i]) |
                 (k1.x == qlo[i]) | (k1.y == qhi[i]) |
                 (k1.z == qlo[i]) | (k1.w == qhi[i]) |
                 (k2.x == qlo[i]) | (k2.y == qhi[i]) |
                 (k2.z == qlo[i]) | (k2.w == qhi[i]) |
                 (k3.x == qlo[i]) | (k3.y == qhi[i]) |
                 (k3.z == qlo[i]) | (k3.w == qhi[i]);
        if (m) susp |= 1u << i;
    }

    if (susp) atomicOr(&s_susp, susp);          // statistically never taken
    __syncthreads();
    unsigned bsusp = s_susp;

    // Block's output region: 16 queries x 64 floats = 4 KB = 256 float4.
    float4  neg = make_float4(-1.0f, -1.0f, -1.0f, -1.0f);
    float4* bo  = (float4*)(out + (size_t)q0 * KMAX);

    if (__builtin_expect(bsusp == 0u, 1)) {     // the certain case
        bo[t] = neg;                            // one coalesced STG.128/thread
        return;
    }

    // ---- RARE PATH ----
    // Blanket -1 for non-suspect queries (float4 t belongs to query t>>4).
    if (!((bsusp >> (t >> 4)) & 1u)) bo[t] = neg;

    // Warp 0 resolves each suspect query with the exact ordered ballot scan.
    if (warp == 0) {
        const uint2* gk = g_keys + (size_t)b * LEN;
        unsigned lt_mask = (1u << lane) - 1u;
        unsigned rem = bsusp;
        while (rem) {
            int i = __ffs((int)rem) - 1;  rem &= rem - 1u;
            unsigned sqlo = qlo[i], sqhi = qhi[i];
            float* so = out + (size_t)(q0 + i) * KMAX;
            int count = 0;
            for (int c = 0; c < LEN / 32; ++c) {
                int j = c * 32 + lane;
                uint2 k = gk[j];
                bool m = (k.x == sqlo) | (k.y == sqhi);
                unsigned mask = __ballot_sync(0xFFFFFFFFu, m);
                if (mask) {
                    int pos = count + __popc(mask & lt_mask);
                    if (m && pos < KMAX) so[pos] = (float)j;
                    count += __popc(mask);
                    if (count >= KMAX) break;   // warp-uniform
                }
            }
            for (int p = count + lane; p < KMAX; p += 32)
                so[p] = -1.0f;
        }
    }
}

// ---------------------------------------------------------------------------
// Launch: inputs = query_up (f32), key_up (f32), head_idx (unused).
// Two graph-capturable launches, no syncs, no allocations.
// ---------------------------------------------------------------------------
extern "C" void kernel_launch(void* const* d_in, const int* in_sizes, int n_in,
                              void* d_out, int out_size) {
    const float* query_up = (const float*)d_in[0];
    const float* key_up   = (const float*)d_in[1];
    float* out = (float*)d_out;

    // 8192 key tokens, 8 warps per 256-thread block -> 1024 blocks
    pack_keys_kernel<<<(BATCH * LEN) / 8, 256>>>(key_up);
    // 16 queries per 256-thread block -> 512 blocks
    find_cands_kernel<<<(BATCH * LEN) / QB, 256>>>(query_up, out);
}

// round 13
// speedup vs baseline: 1.5147x; 1.5147x over previous
#include <cuda_runtime.h>
#include <cstdint>

// Problem constants (fixed by setup_inputs)
#define BATCH 4
#define LEN   2048
#define DIM   64
#define KMAX  64

// Bloom: per group (lo/hi), 2^17 bits = 16 KB -> 32 KB static smem per block.
#define BLG    17
#define BMASK  ((1u << BLG) - 1u)
#define BWORDS (1 << (BLG - 5))            // 4096 words per filter

// Packed sign bits per token: uint2 = (lo d0..31, hi d32..63).
__device__ uint2 g_keys [BATCH * LEN];
__device__ uint2 g_qbits[BATCH * LEN];

// 3 hash functions of a 32-bit word onto 17 bits
__device__ __forceinline__ unsigned h1(unsigned w) { return w & BMASK; }
__device__ __forceinline__ unsigned h2(unsigned w) { return (w >> 15) & BMASK; }
__device__ __forceinline__ unsigned h3(unsigned w) { return (w * 0x9E3779B1u) >> (32 - BLG); }

// ---------------------------------------------------------------------------
// K1: pack sign bits for keys AND queries (one warp per token) and blanket-
// write the whole output with -1.0f (exactly one float per thread, coalesced).
// The output is ~always all -1 (P(32-bit sign match) = 2^-32); K2 fixes up
// the statistically-nonexistent exceptions afterwards (stream-ordered).
// grid = 2048 x 256: 16384 token-warps, 524288 threads = out_size floats.
// ---------------------------------------------------------------------------
__global__ void __launch_bounds__(256)
pack_blank_kernel(const float* __restrict__ query_up,
                  const float* __restrict__ key_up,
                  float* __restrict__ out) {
    int gtid = blockIdx.x * 256 + threadIdx.x;
    out[gtid] = -1.0f;                              // blanket (coalesced)

    int w    = gtid >> 5;                           // token-warp id 0..16383
    int lane = threadIdx.x & 31;
    bool is_q = (w >= BATCH * LEN);
    int  tok  = is_q ? (w - BATCH * LEN) : w;

    const float* p = (is_q ? query_up : key_up) + (size_t)tok * DIM;
    unsigned lo = __ballot_sync(0xFFFFFFFFu, p[lane]      > 0.0f);
    unsigned hi = __ballot_sync(0xFFFFFFFFu, p[lane + 32] > 0.0f);
    if (lane == 0) {
        if (is_q) g_qbits[tok] = make_uint2(lo, hi);
        else      g_keys [tok] = make_uint2(lo, hi);
    }
}

// ---------------------------------------------------------------------------
// K2: one block per batch (4 x 1024). Build a smem Bloom filter (2 groups x
// 2^17 bits, k=3) over the batch's 2048 key words, then probe the 2048
// queries (2 per thread). A query is suspect iff all 3 bits hit in either
// group -- this includes every true match (no false negatives). Expected
// suspects ~1.7 total. Suspects are resolved with the exact ordered ballot
// scan (R7-proven semantics) over g_keys, overwriting K1's blanket -1s.
// Non-suspects: write nothing (blanket already correct).
// ---------------------------------------------------------------------------
__global__ void __launch_bounds__(1024)
verify_kernel(float* __restrict__ out) {
    __shared__ unsigned filt[2][BWORDS];            // 32 KB

    int b    = blockIdx.x;
    int t    = threadIdx.x;
    int lane = t & 31;

    // Zero the filters: 8192 words = 2048 uint4; 2 per thread.
    ((uint4*)filt)[t]        = make_uint4(0u, 0u, 0u, 0u);
    ((uint4*)filt)[t + 1024] = make_uint4(0u, 0u, 0u, 0u);
    __syncthreads();

    // Insert this thread's 2 keys (one LDG.128): lo words -> filt[0],
    // hi words -> filt[1]; 3 hashes each.
    const uint4* gk4 = (const uint4*)(g_keys + (size_t)b * LEN);
    uint4 kk = gk4[t];
    #pragma unroll
    for (int r = 0; r < 2; ++r) {
        unsigned lo = r ? kk.z : kk.x;
        unsigned hi = r ? kk.w : kk.y;
        unsigned a0 = h1(lo), a1 = h2(lo), a2 = h3(lo);
        atomicOr(&filt[0][a0 >> 5], 1u << (a0 & 31));
        atomicOr(&filt[0][a1 >> 5], 1u << (a1 & 31));
        atomicOr(&filt[0][a2 >> 5], 1u << (a2 & 31));
        unsigned c0 = h1(hi), c1 = h2(hi), c2 = h3(hi);
        atomicOr(&filt[1][c0 >> 5], 1u << (c0 & 31));
        atomicOr(&filt[1][c1 >> 5], 1u << (c1 & 31));
        atomicOr(&filt[1][c2 >> 5], 1u << (c2 & 31));
    }
    __syncthreads();

    // Probe this thread's 2 queries (one LDG.128).
    const uint4* gq4 = (const uint4*)(g_qbits + (size_t)b * LEN);
    uint4 qq = gq4[t];

    #define TEST3(f, w) ( ((filt[f][h1(w) >> 5] >> (h1(w) & 31)) & 1u) \
                        & ((filt[f][h2(w) >> 5] >> (h2(w) & 31)) & 1u) \
                        & ((filt[f][h3(w) >> 5] >> (h3(w) & 31)) & 1u) )
    bool s0 = (TEST3(0, qq.x) | TEST3(1, qq.y)) != 0u;   // query 2t
    bool s1 = (TEST3(0, qq.z) | TEST3(1, qq.w)) != 0u;   // query 2t+1

    unsigned m0 = __ballot_sync(0xFFFFFFFFu, s0);
    unsigned m1 = __ballot_sync(0xFFFFFFFFu, s1);
    if (__builtin_expect((m0 | m1) == 0u, 1)) return;    // the certain case

    // ---- RARE PATH: exact ordered ballot scan per suspect query ----
    const uint2* gk = g_keys + (size_t)b * LEN;
    unsigned lt_mask = (1u << lane) - 1u;
    int wbase = (t >> 5) << 6;                           // warp's first query id

    #pragma unroll
    for (int rep = 0; rep < 2; ++rep) {
        unsigned rem = rep ? m1 : m0;
        while (rem) {
            int l = __ffs((int)rem) - 1;  rem &= rem - 1u;
            unsigned sqlo = __shfl_sync(0xFFFFFFFFu, rep ? qq.z : qq.x, l);
            unsigned sqhi = __shfl_sync(0xFFFFFFFFu, rep ? qq.w : qq.y, l);
            int qid = wbase + 2 * l + rep;               // batch-local query id
            float* so = out + ((size_t)b * LEN + qid) * KMAX;
            int count = 0;
            for (int c = 0; c < LEN / 32; ++c) {
                int j = c * 32 + lane;
                uint2 k = gk[j];
                bool m = (k.x == sqlo) | (k.y == sqhi);
                unsigned mask = __ballot_sync(0xFFFFFFFFu, m);
                if (mask) {
                    int pos = count + __popc(mask & lt_mask);
                    if (m && pos < KMAX) so[pos] = (float)j;
                    count += __popc(mask);
                    if (count >= KMAX) break;            // warp-uniform
                }
            }
            // pad (blanket -1 already there; rewrite is harmless/correct)
            for (int p = count + lane; p < KMAX; p += 32)
                so[p] = -1.0f;
        }
    }
    #undef TEST3
}

// ---------------------------------------------------------------------------
// Launch: inputs = query_up (f32), key_up (f32), head_idx (unused).
// Two graph-capturable launches, no syncs, no allocations.
// ---------------------------------------------------------------------------
extern "C" void kernel_launch(void* const* d_in, const int* in_sizes, int n_in,
                              void* d_out, int out_size) {
    const float* query_up = (const float*)d_in[0];
    const float* key_up   = (const float*)d_in[1];
    float* out = (float*)d_out;

    // 16384 token-warps (8192 keys + 8192 queries) AND 524288 = out_size
    // blanket threads in one grid: 2048 blocks x 256 threads.
    pack_blank_kernel<<<2 * BATCH * LEN / 8, 256>>>(query_up, key_up, out);
    // One block per batch builds + probes its Bloom filter, fixes suspects.
    verify_kernel<<<BATCH, 1024>>>(out);
}